// round 2
// baseline (speedup 1.0000x reference)
#include <cuda_runtime.h>
#include <cuda_fp16.h>
#include <stdint.h>

// Problem constants
#define kB 128
#define kT 2048
#define kI 128
#define kH 256
#define kO 128

#define LDA  392   // K=384 padded (mult of 8)
#define LDG2 264   // K=256 padded (mult of 8)

// Persistent device state (zero-initialized at module load)
__device__ __half g_h1[2][2][kB][kH];   // [dir][parity][b][h]
__device__ __half g_h2[2][2][kB][kH];
__device__ float  g_hf[2][kB][kH];      // final h2 fp32
__device__ unsigned g_cnt[4];
__device__ unsigned g_epoch[4];

struct SM {
    __half wL[64][LDA];     // LSTM weight slice: rows = gate*16+u, cols 0..127 w1x, 128..383 w1h
    __half w2x[48][LDG2];   // GRU x-weights slice
    __half w2h[48][LDG2];   // GRU h-weights slice
    __half aL[32][LDA];     // A for LSTM: [x_t fp16 | h1 fp16]
    __half a2[32][LDG2];    // A2 = h2(prev)
    float accL[32][64];
    float accX[32][48];
    float accH[32][48];
    float c1[32][16];       // fp32 LSTM cell state (resident)
    float h2l[32][16];      // fp32 GRU hidden (resident)
    float bL[64];
    float b2xs[48];
    float b2hs[48];
};

__device__ __forceinline__ float sigf(float x) { return 1.0f / (1.0f + __expf(-x)); }

__device__ __forceinline__ unsigned ld_acq(unsigned* p) {
    unsigned v;
    asm volatile("ld.acquire.gpu.u32 %0, [%1];" : "=r"(v) : "l"(p));
    return v;
}

// Sense-reversal inter-CTA barrier (cooperative-groups pattern)
__device__ __forceinline__ void gbar(int slot, unsigned target) {
    __syncthreads();
    if (threadIdx.x == 0) {
        __threadfence();
        unsigned e = ld_acq(&g_epoch[slot]);
        unsigned old = atomicAdd(&g_cnt[slot], 1u);
        if (old == target - 1u) {
            g_cnt[slot] = 0u;
            __threadfence();
            atomicAdd(&g_epoch[slot], 1u);
        } else {
            while (ld_acq(&g_epoch[slot]) == e) { }
        }
    }
    __syncthreads();
}

// ldmatrix helpers
__device__ __forceinline__ unsigned sptr(const void* p) {
    return (unsigned)__cvta_generic_to_shared(p);
}

__device__ __forceinline__ void lda16x16(unsigned* r, const __half* base, int lda) {
    int lane = threadIdx.x & 31;
    const __half* p = base + (lane & 15) * lda + (lane >> 4) * 8;
    unsigned a = sptr(p);
    asm volatile("ldmatrix.sync.aligned.m8n8.x4.shared.b16 {%0,%1,%2,%3},[%4];"
                 : "=r"(r[0]), "=r"(r[1]), "=r"(r[2]), "=r"(r[3]) : "r"(a));
}

__device__ __forceinline__ void ldb16x8(unsigned* r, const __half* base, int ldb) {
    int lane = threadIdx.x & 31;
    int l = lane & 15;
    const __half* p = base + (l & 7) * ldb + (l >> 3) * 8;
    unsigned a = sptr(p);
    asm volatile("ldmatrix.sync.aligned.m8n8.x2.shared.b16 {%0,%1},[%2];"
                 : "=r"(r[0]), "=r"(r[1]) : "r"(a));
}

__device__ __forceinline__ void mma16816(float* c, const unsigned* a, const unsigned* b) {
    asm volatile("mma.sync.aligned.m16n8k16.row.col.f32.f16.f16.f32 "
                 "{%0,%1,%2,%3},{%4,%5,%6,%7},{%8,%9},{%0,%1,%2,%3};"
                 : "+f"(c[0]), "+f"(c[1]), "+f"(c[2]), "+f"(c[3])
                 : "r"(a[0]), "r"(a[1]), "r"(a[2]), "r"(a[3]), "r"(b[0]), "r"(b[1]));
}

__device__ __forceinline__ void stacc(float* dst, int ldc, const float* c) {
    int lane = threadIdx.x & 31;
    int r = lane >> 2, col = (lane & 3) * 2;
    dst[r * ldc + col]           = c[0];
    dst[r * ldc + col + 1]       = c[1];
    dst[(r + 8) * ldc + col]     = c[2];
    dst[(r + 8) * ldc + col + 1] = c[3];
}

__global__ void __launch_bounds__(256, 1) brnn_kernel(
    const float* __restrict__ x,
    const float* __restrict__ w1x, const float* __restrict__ b1x,
    const float* __restrict__ w1h, const float* __restrict__ b1h,
    const float* __restrict__ w2x, const float* __restrict__ b2x,
    const float* __restrict__ w2h, const float* __restrict__ b2h,
    const float* __restrict__ wo,  const float* __restrict__ bo,
    float* __restrict__ out)
{
    extern __shared__ __align__(16) char smraw[];
    SM& s = *reinterpret_cast<SM*>(smraw);
    const int tid = threadIdx.x;
    const int d = blockIdx.x >> 6;       // direction
    const int g = blockIdx.x & 63;
    const int bg = g & 3, ng = g >> 2;
    const int row0 = bg * 32, hu0 = ng * 16;

    // ---- load weight slices to SMEM (fp16) ----
    for (int idx = tid; idx < 64 * 384; idx += 256) {
        int r = idx / 384, cc = idx - r * 384;
        int gate = r >> 4, u = r & 15;
        int gr = gate * kH + hu0 + u;
        float v = (cc < kI) ? w1x[gr * kI + cc] : w1h[gr * kH + (cc - kI)];
        s.wL[r][cc] = __float2half_rn(v);
    }
    for (int idx = tid; idx < 48 * 256; idx += 256) {
        int r = idx >> 8, cc = idx & 255;
        int gate = r >> 4, u = r & 15;
        int gr = gate * kH + hu0 + u;
        s.w2x[r][cc] = __float2half_rn(w2x[gr * kH + cc]);
        s.w2h[r][cc] = __float2half_rn(w2h[gr * kH + cc]);
    }
    if (tid < 64) {
        int gate = tid >> 4, u = tid & 15;
        int gr = gate * kH + hu0 + u;
        s.bL[tid] = b1x[gr] + b1h[gr];
    }
    if (tid < 48) {
        int gate = tid >> 4, u = tid & 15;
        int gr = gate * kH + hu0 + u;
        s.b2xs[tid] = b2x[gr];
        s.b2hs[tid] = b2h[gr];
    }
    // zero resident state + my slice of parity-0 global state
    for (int idx = tid; idx < 512; idx += 256) {
        int b = idx >> 4, u = idx & 15;
        s.c1[b][u] = 0.f;
        s.h2l[b][u] = 0.f;
        g_h1[d][0][row0 + b][hu0 + u] = __float2half_rn(0.f);
        g_h2[d][0][row0 + b][hu0 + u] = __float2half_rn(0.f);
    }
    gbar(d, 64);

    const int r8 = tid >> 3, j8 = tid & 7;

    // ---- main recurrence: iteration k computes h1(k+1) and h2(k) ----
    for (int k = 0; k <= kT; k++) {
        const int par = k & 1;

        // stage x_t (fp32->fp16) into aL cols [0,128)
        if (k < kT) {
            const int t = d ? (kT - 1 - k) : k;
            const float4* xs = (const float4*)(x + ((size_t)(row0 + r8) * kT + t) * kI) + j8 * 4;
            __half2* dst = (__half2*)&s.aL[r8][j8 * 16];
            #pragma unroll
            for (int q = 0; q < 4; q++) {
                float4 f = __ldg(xs + q);
                dst[q * 2]     = __floats2half2_rn(f.x, f.y);
                dst[q * 2 + 1] = __floats2half2_rn(f.z, f.w);
            }
        }
        // stage h1(k) into aL cols [128,384) and h2(k-1) into a2 (L2 reads)
        {
            const uint4* s1 = (const uint4*)&g_h1[d][par][row0 + r8][0] + j8 * 4;
            uint4* d1 = (uint4*)&s.aL[r8][128] + j8 * 4;
            const uint4* s2 = (const uint4*)&g_h2[d][par][row0 + r8][0] + j8 * 4;
            uint4* d2 = (uint4*)&s.a2[r8][0] + j8 * 4;
            #pragma unroll
            for (int q = 0; q < 4; q++) {
                d1[q] = __ldcg(s1 + q);
                d2[q] = __ldcg(s2 + q);
            }
        }
        __syncthreads();

        const int w = tid >> 5;
        // LSTM gates GEMM: [32,384] x [384,64]
        if (k < kT) {
            for (int tile = w; tile < 16; tile += 8) {
                int mt = tile & 1, nt = tile >> 1;
                float c[4] = {0.f, 0.f, 0.f, 0.f};
                #pragma unroll
                for (int kk = 0; kk < 24; kk++) {
                    unsigned a[4], b[2];
                    lda16x16(a, &s.aL[mt * 16][kk * 16], LDA);
                    ldb16x8(b, &s.wL[nt * 8][kk * 16], LDA);
                    mma16816(c, a, b);
                }
                stacc(&s.accL[mt * 16][nt * 8], 64, c);
            }
        }
        // GRU GEMMs: x-part uses h1(k) (= aL h columns), h-part uses h2(k-1)
        for (int tt = w; tt < 24; tt += 8) {
            int which = tt / 12, rem = tt - which * 12;
            int mt = rem & 1, nt = rem >> 1;
            const __half* A = which ? &s.a2[mt * 16][0] : &s.aL[mt * 16][128];
            int ld = which ? LDG2 : LDA;
            const __half* Wt = which ? &s.w2h[nt * 8][0] : &s.w2x[nt * 8][0];
            float c[4] = {0.f, 0.f, 0.f, 0.f};
            #pragma unroll
            for (int kk = 0; kk < 16; kk++) {
                unsigned a[4], b[2];
                lda16x16(a, A + kk * 16, ld);
                ldb16x8(b, Wt + kk * 16, LDG2);
                mma16816(c, a, b);
            }
            stacc(which ? &s.accH[mt * 16][nt * 8] : &s.accX[mt * 16][nt * 8], 48, c);
        }
        __syncthreads();

        // LSTM elementwise + write h1(k+1)
        if (k < kT) {
            for (int it = tid; it < 512; it += 256) {
                int b = it >> 4, u = it & 15;
                float ig = sigf(s.accL[b][u]          + s.bL[u]);
                float fg = sigf(s.accL[b][16 + u]     + s.bL[16 + u]);
                float gg = tanhf(s.accL[b][32 + u]    + s.bL[32 + u]);
                float og = sigf(s.accL[b][48 + u]     + s.bL[48 + u]);
                float c  = s.c1[b][u] * fg + ig * gg;
                s.c1[b][u] = c;
                g_h1[d][par ^ 1][row0 + b][hu0 + u] = __float2half_rn(og * tanhf(c));
            }
        }
        // GRU elementwise + write h2(k)
        for (int it = tid; it < 512; it += 256) {
            int b = it >> 4, u = it & 15;
            float rr = sigf(s.accX[b][u]       + s.b2xs[u]      + s.accH[b][u]      + s.b2hs[u]);
            float zz = sigf(s.accX[b][16 + u]  + s.b2xs[16 + u] + s.accH[b][16 + u] + s.b2hs[16 + u]);
            float hn = s.accH[b][32 + u] + s.b2hs[32 + u];
            float nn = tanhf(s.accX[b][32 + u] + s.b2xs[32 + u] + rr * hn);
            float h2 = zz * s.h2l[b][u] + (1.f - zz) * nn;
            s.h2l[b][u] = h2;
            g_h2[d][par ^ 1][row0 + b][hu0 + u] = __float2half_rn(h2);
            if (k == kT) g_hf[d][row0 + b][hu0 + u] = h2;
        }

        gbar(d, 64);
    }

    // ---- final FC: out = [h_fwd | h_bwd] @ wo^T + bo ----
    gbar(2, 128);
    if (blockIdx.x < 16) {
        float* sh = (float*)&s;              // reuse SMEM: [8][512]
        int b0r = blockIdx.x * 8;
        for (int idx = tid; idx < 8 * 512; idx += 256) {
            int br = idx >> 9, j = idx & 511;
            sh[idx] = (j < 256) ? __ldcg(&g_hf[0][b0r + br][j])
                                : __ldcg(&g_hf[1][b0r + br][j - 256]);
        }
        __syncthreads();
        for (int it = tid; it < 8 * 128; it += 256) {
            int br = it >> 7, o = it & 127;
            float acc = bo[o];
            const float* wrow = wo + o * 512;
            const float* hrow = sh + br * 512;
            #pragma unroll 8
            for (int j = 0; j < 512; j++) acc += hrow[j] * wrow[j];
            out[(size_t)(b0r + br) * kO + o] = acc;
        }
    }
}

extern "C" void kernel_launch(void* const* d_in, const int* in_sizes, int n_in,
                              void* d_out, int out_size)
{
    const float* x   = (const float*)d_in[0];
    const float* w1x = (const float*)d_in[1];
    const float* b1x = (const float*)d_in[2];
    const float* w1h = (const float*)d_in[3];
    const float* b1h = (const float*)d_in[4];
    const float* w2x = (const float*)d_in[5];
    const float* b2x = (const float*)d_in[6];
    const float* w2h = (const float*)d_in[7];
    const float* b2h = (const float*)d_in[8];
    const float* wo  = (const float*)d_in[9];
    const float* bo  = (const float*)d_in[10];

    cudaFuncSetAttribute(brnn_kernel, cudaFuncAttributeMaxDynamicSharedMemorySize,
                         (int)sizeof(SM));
    brnn_kernel<<<128, 256, sizeof(SM)>>>(x, w1x, b1x, w1h, b1h,
                                          w2x, b2x, w2h, b2h, wo, bo,
                                          (float*)d_out);
}

// round 3
// speedup vs baseline: 1.3857x; 1.3857x over previous
#include <cuda_runtime.h>
#include <cuda_fp16.h>
#include <stdint.h>

// Problem constants
#define kB 128
#define kT 2048
#define kI 128
#define kH 256
#define kO 128

#define LDA  392   // K=384 padded (mult of 8, conflict-free for ldmatrix)
#define LDG2 264   // K=256 padded

// Persistent device state (zero-initialized at module load)
__device__ __half g_h1[2][2][kB][kH];   // [dir][parity][b][h]
__device__ __half g_h2[2][2][kB][kH];
__device__ float  g_hf[2][kB][kH];      // final h2 fp32
__device__ unsigned g_flag[8][32];      // [group][ng] epoch flags (reset at kernel end)
__device__ unsigned g_cnt[4];
__device__ unsigned g_epoch[4];

struct SM {
    __half wL[64][LDA];     // LSTM weight slice: rows = gate*16+u, cols [0,128)=w1x, [128,384)=w1h
    __half w2x[48][LDG2];   // GRU x-weights slice
    __half w2h[48][LDG2];   // GRU h-weights slice
    __half aL[32][LDA];     // A for LSTM: [x_t | h1]
    __half a2[32][LDG2];    // A2 = h2(prev)
    float accL[32][64];
    float accX[32][48];
    float accH[32][48];
    float c1[32][16];       // fp32 LSTM cell state (SM-resident)
    float h2l[32][16];      // fp32 GRU hidden (SM-resident)
    float bL[64];
    float b2xs[48];
    float b2hs[48];
};

__device__ __forceinline__ float sigf(float x) { return 1.0f / (1.0f + __expf(-x)); }

__device__ __forceinline__ unsigned ld_acq(const unsigned* p) {
    unsigned v;
    asm volatile("ld.acquire.gpu.u32 %0, [%1];" : "=r"(v) : "l"(p) : "memory");
    return v;
}
__device__ __forceinline__ void st_rel(unsigned* p, unsigned v) {
    asm volatile("st.release.gpu.u32 [%0], %1;" :: "l"(p), "r"(v) : "memory");
}

// All-CTA sense-reversal barrier (used twice: end of recurrence)
__device__ __forceinline__ void gbar_all(int slot, unsigned target) {
    __syncthreads();
    if (threadIdx.x == 0) {
        __threadfence();
        unsigned e = ld_acq(&g_epoch[slot]);
        unsigned old = atomicAdd(&g_cnt[slot], 1u);
        if (old == target - 1u) {
            g_cnt[slot] = 0u;
            __threadfence();
            atomicAdd(&g_epoch[slot], 1u);
        } else {
            while (ld_acq(&g_epoch[slot]) == e) { }
        }
    }
    __syncthreads();
}

// ldmatrix helpers
__device__ __forceinline__ unsigned sptr(const void* p) {
    return (unsigned)__cvta_generic_to_shared(p);
}
__device__ __forceinline__ void lda16x16(unsigned* r, const __half* base, int lda) {
    int lane = threadIdx.x & 31;
    const __half* p = base + (lane & 15) * lda + (lane >> 4) * 8;
    unsigned a = sptr(p);
    asm volatile("ldmatrix.sync.aligned.m8n8.x4.shared.b16 {%0,%1,%2,%3},[%4];"
                 : "=r"(r[0]), "=r"(r[1]), "=r"(r[2]), "=r"(r[3]) : "r"(a));
}
__device__ __forceinline__ void ldb16x8(unsigned* r, const __half* base, int ldb) {
    int lane = threadIdx.x & 31;
    int l = lane & 15;
    const __half* p = base + (l & 7) * ldb + (l >> 3) * 8;
    unsigned a = sptr(p);
    asm volatile("ldmatrix.sync.aligned.m8n8.x2.shared.b16 {%0,%1},[%2];"
                 : "=r"(r[0]), "=r"(r[1]) : "r"(a));
}
__device__ __forceinline__ void mma16816(float* c, const unsigned* a, const unsigned* b) {
    asm volatile("mma.sync.aligned.m16n8k16.row.col.f32.f16.f16.f32 "
                 "{%0,%1,%2,%3},{%4,%5,%6,%7},{%8,%9},{%0,%1,%2,%3};"
                 : "+f"(c[0]), "+f"(c[1]), "+f"(c[2]), "+f"(c[3])
                 : "r"(a[0]), "r"(a[1]), "r"(a[2]), "r"(a[3]), "r"(b[0]), "r"(b[1]));
}
__device__ __forceinline__ void stacc(float* dst, int ldc, const float* c) {
    int lane = threadIdx.x & 31;
    int r = lane >> 2, col = (lane & 3) * 2;
    dst[r * ldc + col]           = c[0];
    dst[r * ldc + col + 1]       = c[1];
    dst[(r + 8) * ldc + col]     = c[2];
    dst[(r + 8) * ldc + col + 1] = c[3];
}

__global__ void __launch_bounds__(256, 1) brnn_kernel(
    const float* __restrict__ x,
    const float* __restrict__ w1x, const float* __restrict__ b1x,
    const float* __restrict__ w1h, const float* __restrict__ b1h,
    const float* __restrict__ w2x, const float* __restrict__ b2x,
    const float* __restrict__ w2h, const float* __restrict__ b2h,
    const float* __restrict__ wo,  const float* __restrict__ bo,
    float* __restrict__ out)
{
    extern __shared__ __align__(16) char smraw[];
    SM& s = *reinterpret_cast<SM*>(smraw);
    const int tid = threadIdx.x;
    const int d = blockIdx.x >> 6;       // direction
    const int g = blockIdx.x & 63;
    const int bg = g & 3, ng = g >> 2;   // batch-group (32 rows), hidden-group (16 units)
    const int row0 = bg * 32, hu0 = ng * 16;
    const int grp = d * 4 + bg;          // 16-CTA communication group

    // ---- load weight slices to SMEM (fp16) ----
    for (int idx = tid; idx < 64 * 384; idx += 256) {
        int r = idx / 384, cc = idx - r * 384;
        int gate = r >> 4, u = r & 15;
        int gr = gate * kH + hu0 + u;
        float v = (cc < kI) ? w1x[gr * kI + cc] : w1h[gr * kH + (cc - kI)];
        s.wL[r][cc] = __float2half_rn(v);
    }
    for (int idx = tid; idx < 48 * 256; idx += 256) {
        int r = idx >> 8, cc = idx & 255;
        int gate = r >> 4, u = r & 15;
        int gr = gate * kH + hu0 + u;
        s.w2x[r][cc] = __float2half_rn(w2x[gr * kH + cc]);
        s.w2h[r][cc] = __float2half_rn(w2h[gr * kH + cc]);
    }
    if (tid < 64) {
        int gate = tid >> 4, u = tid & 15;
        int gr = gate * kH + hu0 + u;
        s.bL[tid] = b1x[gr] + b1h[gr];
    }
    if (tid < 48) {
        int gate = tid >> 4, u = tid & 15;
        int gr = gate * kH + hu0 + u;
        s.b2xs[tid] = b2x[gr];
        s.b2hs[tid] = b2h[gr];
    }
    // zero resident state + my slice of parity-0 global state
    for (int idx = tid; idx < 512; idx += 256) {
        int b = idx >> 4, u = idx & 15;
        s.c1[b][u] = 0.f;
        s.h2l[b][u] = 0.f;
        g_h1[d][0][row0 + b][hu0 + u] = __float2half_rn(0.f);
        g_h2[d][0][row0 + b][hu0 + u] = __float2half_rn(0.f);
    }

    const int r8 = tid >> 3, j8 = tid & 7;
    unsigned ep = 1;

    // initial group barrier (zero-init visibility); overlap x(0) staging with it
    __threadfence();
    __syncthreads();
    if (tid == 0) st_rel(&g_flag[grp][ng], ep);
    {
        const int t = d ? (kT - 1) : 0;
        const float4* xs = (const float4*)(x + ((size_t)(row0 + r8) * kT + t) * kI) + j8 * 4;
        __half2* dst = (__half2*)&s.aL[r8][j8 * 16];
        #pragma unroll
        for (int q = 0; q < 4; q++) {
            float4 f = __ldg(xs + q);
            dst[q * 2]     = __floats2half2_rn(f.x, f.y);
            dst[q * 2 + 1] = __floats2half2_rn(f.z, f.w);
        }
    }
    if (tid < 16) {
        const unsigned* fp = &g_flag[grp][tid];
        while (ld_acq(fp) < ep) { }
    }
    __syncthreads();

    // ---- main recurrence: iteration k computes h1(k+1) and h2(k) ----
    for (int k = 0; k <= kT; k++) {
        const int par = k & 1;

        // stage h1(k) -> aL cols [128,384), h2(k-1) -> a2 (L2 reads)
        {
            const uint4* s1 = (const uint4*)&g_h1[d][par][row0 + r8][0] + j8 * 4;
            uint4* d1 = (uint4*)&s.aL[r8][128] + j8 * 4;
            const uint4* s2 = (const uint4*)&g_h2[d][par][row0 + r8][0] + j8 * 4;
            uint4* d2 = (uint4*)&s.a2[r8][0] + j8 * 4;
            #pragma unroll
            for (int q = 0; q < 4; q++) {
                d1[q] = __ldcg(s1 + q);
                d2[q] = __ldcg(s2 + q);
            }
        }
        __syncthreads();

        const int w = tid >> 5;
        if (w < 4) {
            // LSTM gates GEMM: [32,384] x [384,64]; warp = (m16, n32)
            if (k < kT) {
                const int mt = w & 1, ng2 = w >> 1;
                float acc[4][4] = {};
                const __half* Abase = &s.aL[mt * 16][0];
                const __half* Bbase = &s.wL[ng2 * 32][0];
                #pragma unroll
                for (int kk = 0; kk < 24; kk++) {
                    unsigned a[4];
                    lda16x16(a, Abase + kk * 16, LDA);
                    #pragma unroll
                    for (int nt = 0; nt < 4; nt++) {
                        unsigned b[2];
                        ldb16x8(b, Bbase + nt * 8 * LDA + kk * 16, LDA);
                        mma16816(acc[nt], a, b);
                    }
                }
                #pragma unroll
                for (int nt = 0; nt < 4; nt++)
                    stacc(&s.accL[mt * 16][ng2 * 32 + nt * 8], 64, acc[nt]);
            }
        } else {
            // GRU GEMMs: warp = (m16, n48) for one of {x-part (A=h1), h-part (A=h2)}
            const int mt = w & 1, which = (w >> 1) & 1;
            const __half* A = which ? &s.a2[mt * 16][0] : &s.aL[mt * 16][128];
            const int ld = which ? LDG2 : LDA;
            const __half* Wt = which ? &s.w2h[0][0] : &s.w2x[0][0];
            float acc[6][4] = {};
            #pragma unroll
            for (int kk = 0; kk < 16; kk++) {
                unsigned a[4];
                lda16x16(a, A + kk * 16, ld);
                #pragma unroll
                for (int nt = 0; nt < 6; nt++) {
                    unsigned b[2];
                    ldb16x8(b, Wt + nt * 8 * LDG2 + kk * 16, LDG2);
                    mma16816(acc[nt], a, b);
                }
            }
            float* dst = which ? &s.accH[mt * 16][0] : &s.accX[mt * 16][0];
            #pragma unroll
            for (int nt = 0; nt < 6; nt++)
                stacc(dst + nt * 8, 48, acc[nt]);
        }
        __syncthreads();

        // elementwise: one thread handles (b, u0..u0+1); half2 stores
        {
            const int b = tid >> 3, u0 = (tid & 7) * 2;
            if (k < kT) {
                float h1v[2];
                #pragma unroll
                for (int q = 0; q < 2; q++) {
                    int u = u0 + q;
                    float ig = sigf(s.accL[b][u]       + s.bL[u]);
                    float fg = sigf(s.accL[b][16 + u]  + s.bL[16 + u]);
                    float gg = tanhf(s.accL[b][32 + u] + s.bL[32 + u]);
                    float og = sigf(s.accL[b][48 + u]  + s.bL[48 + u]);
                    float c  = s.c1[b][u] * fg + ig * gg;
                    s.c1[b][u] = c;
                    h1v[q] = og * tanhf(c);
                }
                *(__half2*)&g_h1[d][par ^ 1][row0 + b][hu0 + u0] =
                    __floats2half2_rn(h1v[0], h1v[1]);
            }
            float h2v[2];
            #pragma unroll
            for (int q = 0; q < 2; q++) {
                int u = u0 + q;
                float rr = sigf(s.accX[b][u]      + s.b2xs[u]      + s.accH[b][u]      + s.b2hs[u]);
                float zz = sigf(s.accX[b][16 + u] + s.b2xs[16 + u] + s.accH[b][16 + u] + s.b2hs[16 + u]);
                float hn = s.accH[b][32 + u] + s.b2hs[32 + u];
                float nn = tanhf(s.accX[b][32 + u] + s.b2xs[32 + u] + rr * hn);
                float h2 = zz * s.h2l[b][u] + (1.f - zz) * nn;
                s.h2l[b][u] = h2;
                h2v[q] = h2;
            }
            *(__half2*)&g_h2[d][par ^ 1][row0 + b][hu0 + u0] =
                __floats2half2_rn(h2v[0], h2v[1]);
            if (k == kT) {
                g_hf[d][row0 + b][hu0 + u0]     = h2v[0];
                g_hf[d][row0 + b][hu0 + u0 + 1] = h2v[1];
            }
        }

        if (k == kT) break;   // no more group barriers needed

        // group barrier: arrive, prefetch x(k+1) across the wait, then wait
        __threadfence();
        __syncthreads();
        ep++;
        if (tid == 0) st_rel(&g_flag[grp][ng], ep);
        if (k + 1 < kT) {
            const int t = d ? (kT - 2 - k) : (k + 1);
            const float4* xs = (const float4*)(x + ((size_t)(row0 + r8) * kT + t) * kI) + j8 * 4;
            __half2* dst = (__half2*)&s.aL[r8][j8 * 16];
            #pragma unroll
            for (int q = 0; q < 4; q++) {
                float4 f = __ldg(xs + q);
                dst[q * 2]     = __floats2half2_rn(f.x, f.y);
                dst[q * 2 + 1] = __floats2half2_rn(f.z, f.w);
            }
        }
        if (tid < 16) {
            const unsigned* fp = &g_flag[grp][tid];
            while (ld_acq(fp) < ep) { }
        }
        __syncthreads();
    }

    // ---- all-CTA barrier, reset flags for next launch ----
    __threadfence();
    gbar_all(2, 128);
    if (tid == 0) g_flag[grp][ng] = 0;

    // ---- final FC: out = [h_fwd | h_bwd] @ wo^T + bo ----
    if (blockIdx.x < 16) {
        float* sh = (float*)&s;              // reuse SMEM: [8][512]
        int b0r = blockIdx.x * 8;
        for (int idx = tid; idx < 8 * 512; idx += 256) {
            int br = idx >> 9, j = idx & 511;
            sh[idx] = (j < 256) ? __ldcg(&g_hf[0][b0r + br][j])
                                : __ldcg(&g_hf[1][b0r + br][j - 256]);
        }
        __syncthreads();
        for (int it = tid; it < 8 * 128; it += 256) {
            int br = it >> 7, o = it & 127;
            float acc = bo[o];
            const float* wrow = wo + o * 512;
            const float* hrow = sh + br * 512;
            #pragma unroll 8
            for (int j = 0; j < 512; j++) acc += hrow[j] * wrow[j];
            out[(size_t)(b0r + br) * kO + o] = acc;
        }
    }
}

extern "C" void kernel_launch(void* const* d_in, const int* in_sizes, int n_in,
                              void* d_out, int out_size)
{
    const float* x   = (const float*)d_in[0];
    const float* w1x = (const float*)d_in[1];
    const float* b1x = (const float*)d_in[2];
    const float* w1h = (const float*)d_in[3];
    const float* b1h = (const float*)d_in[4];
    const float* w2x = (const float*)d_in[5];
    const float* b2x = (const float*)d_in[6];
    const float* w2h = (const float*)d_in[7];
    const float* b2h = (const float*)d_in[8];
    const float* wo  = (const float*)d_in[9];
    const float* bo  = (const float*)d_in[10];

    cudaFuncSetAttribute(brnn_kernel, cudaFuncAttributeMaxDynamicSharedMemorySize,
                         (int)sizeof(SM));
    brnn_kernel<<<128, 256, sizeof(SM)>>>(x, w1x, b1x, w1h, b1h,
                                          w2x, b2x, w2h, b2h, wo, bo,
                                          (float*)d_out);
}